// round 14
// baseline (speedup 1.0000x reference)
#include <cuda_runtime.h>
#include <cuda_fp16.h>
#include <cstdint>

#define Hh 192
#define Ww 192
#define HWsz (192*192)
#define Cc 32
#define Tt 8
#define KK 9

// Channels-last fp16 scratch, FRAGMENT-PERMUTED channel order:
// 16B group tq of each 64B pixel row holds channels
// {2tq, 2tq+1, 2tq+8, 2tq+9, 2tq+16, 2tq+17, 2tq+24, 2tq+25}.  (37.7 MB)
__device__ __half g_scratch_h[(size_t)2 * Tt * HWsz * Cc];
// fp16 weights in m16n8k16 fragment order: [t][tap][ks(2)][nt(4)][lane(32)][2]
__device__ uint32_t g_wfrag[(size_t)Tt * KK * 2 * 4 * 32 * 2];

__device__ __forceinline__ void mma_f16(float* c, uint32_t a0, uint32_t a1,
                                        uint32_t a2, uint32_t a3,
                                        uint32_t b0, uint32_t b1) {
    asm volatile(
        "mma.sync.aligned.m16n8k16.row.col.f32.f16.f16.f32 "
        "{%0,%1,%2,%3}, {%4,%5,%6,%7}, {%8,%9}, {%0,%1,%2,%3};"
        : "+f"(c[0]), "+f"(c[1]), "+f"(c[2]), "+f"(c[3])
        : "r"(a0), "r"(a1), "r"(a2), "r"(a3), "r"(b0), "r"(b1));
}

// Bilinear-combine one pixel's 8 fragment channels from 4 corner slices.
__device__ __forceinline__ void combine8(const uint4& qa, const uint4& qb,
                                         const uint4& qc, const uint4& qd,
                                         const uint4& wq, float* vs) {
    const float u00 = __uint_as_float(wq.x);
    const float u01 = __uint_as_float(wq.y);
    const float u10 = __uint_as_float(wq.z);
    const float u11 = __uint_as_float(wq.w);
    #pragma unroll
    for (int j = 0; j < 4; j++) {
        const float2 fa = __half22float2(((const __half2*)&qa)[j]);
        const float2 fb = __half22float2(((const __half2*)&qb)[j]);
        const float2 fc = __half22float2(((const __half2*)&qc)[j]);
        const float2 fd = __half22float2(((const __half2*)&qd)[j]);
        vs[2 * j]     = fmaf(u00, fa.x, fmaf(u01, fb.x, fmaf(u10, fc.x, u11 * fd.x)));
        vs[2 * j + 1] = fmaf(u00, fa.y, fmaf(u01, fb.y, fmaf(u10, fc.y, u11 * fd.y)));
    }
}

// ---------- Kernel 1: transpose 128hw x 32c tiles (+ weight prep at x==288) ----------
#define TSTRIDE 133
__global__ __launch_bounds__(256) void prep_k(const float* __restrict__ feat,
                                              const float* __restrict__ weight) {
    if (blockIdx.x == 288) {
        const int t = blockIdx.y >> 1;
        const int half = blockIdx.y & 1;
        for (int it = half * 9; it < half * 9 + 9; it++) {
            const int j = it * 256 + threadIdx.x;    // j < 4608
            const int reg  = j & 1;
            const int lane = (j >> 1) & 31;
            const int nt   = (j >> 6) & 3;
            const int ks   = (j >> 8) & 1;
            const int tap  = j >> 9;                 // 0..8
            const int r0 = lane >> 2, c0 = lane & 3;
            const int cout = nt * 8 + r0;
            const int cin0 = ks * 16 + 2 * c0 + reg * 8;
            const float w0 = weight[((size_t)(t * Cc + cout) * Cc + cin0) * KK + tap];
            const float w1 = weight[((size_t)(t * Cc + cout) * Cc + cin0 + 1) * KK + tap];
            const __half2 h = __floats2half2_rn(w0, w1);
            g_wfrag[(size_t)t * 4608 + j] = *(const uint32_t*)&h;
        }
        return;
    }
    __shared__ float tl[32 * TSTRIDE];
    const int tid = threadIdx.x;
    const int bt = blockIdx.y;
    const int b = bt >> 3, t = bt & 7;
    const int hw0 = blockIdx.x * 128;

    const int c  = tid >> 3;
    const int f4 = tid & 7;
    const float* fsrc = feat + ((size_t)(b * Cc + c) * Tt + t) * HWsz + hw0;
    #pragma unroll
    for (int j = 0; j < 4; j++) {
        const float4 v = *(const float4*)(fsrc + (f4 + 8 * j) * 4);
        const int col = (f4 + 8 * j) * 4;
        tl[c * TSTRIDE + col]     = v.x;
        tl[c * TSTRIDE + col + 1] = v.y;
        tl[c * TSTRIDE + col + 2] = v.z;
        tl[c * TSTRIDE + col + 3] = v.w;
    }
    __syncthreads();

    // Write fragment-permuted channel order: group cp4 half2 q = channels
    // (2*cp4 + 8*q, 2*cp4 + 8*q + 1).
    uint32_t* gdst = (uint32_t*)g_scratch_h + ((size_t)bt * HWsz + hw0) * 16;
    #pragma unroll
    for (int jj = 0; jj < 2; jj++) {
        const int u4 = tid + 256 * jj;   // 0..511
        const int hw = u4 >> 2;
        const int cp4 = u4 & 3;
        uint4 o;
        uint32_t* op = &o.x;
        #pragma unroll
        for (int q = 0; q < 4; q++) {
            const int ch = 2 * cp4 + 8 * q;
            const __half2 h = __floats2half2_rn(tl[ch * TSTRIDE + hw],
                                                tl[(ch + 1) * TSTRIDE + hw]);
            op[q] = *(const uint32_t*)&h;
        }
        *(uint4*)(gdst + hw * 16 + cp4 * 4) = o;
    }
}

// ---------- Kernel 2: fused deform-sample + mma.sync fp16 GEMM ----------
// Per-warp tile: 16 pixels x 32 cout. CTA = 8 warps = 128 pixels.
// A fragments built directly in registers (no A smem slab).
// smem: params 8w x 16 x 12 u32 = 6144B; epilogue D 32x132 f32 = 16896B reuses it.
#define PPAD 12
#define DPAD 132
#define SM_TOTAL 16896

__global__ __launch_bounds__(256, 4) void dcn_main(
    const float* __restrict__ offset,   // [B, 18, T, H, W]
    float* __restrict__ out)            // [B, 32, T, H, W]
{
    extern __shared__ char smem[];
    const int tid  = threadIdx.x;
    const int wid  = tid >> 5;
    const int lane = tid & 31;
    const int bt = blockIdx.y;
    const int b = bt >> 3, t = bt & 7;
    const int pix0  = blockIdx.x * 128;
    const int pixw0 = pix0 + wid * 16;

    uint32_t* sp = (uint32_t*)smem + wid * (16 * PPAD);   // params
    const float* offb = offset + ((size_t)b * 2 * KK * Tt + t) * HWsz + pixw0 + (lane & 15);
    const uint32_t* gwf = g_wfrag + (size_t)t * 4608 + lane * 2;
    // Gather base: this lane's fragment 16B slice of each 64B pixel row.
    const uint4* gb4 = (const uint4*)g_scratch_h + (size_t)bt * HWsz * 4 + (lane & 3);

    const int g  = lane >> 2;     // fragment group: pixels g and g+8
    const int mypix = pixw0 + (lane & 15);
    const int myh = (int)((unsigned)mypix / Ww);
    const int myw = mypix - myh * Ww;
    const size_t ostr = (size_t)Tt * HWsz;

    float acc[4][4];
    #pragma unroll
    for (int n = 0; n < 4; n++)
        #pragma unroll
        for (int r = 0; r < 4; r++) acc[n][r] = 0.f;

    #pragma unroll 1
    for (int k = 0; k < KK; k++) {
        // ---- Phase A: per-lane bilinear params (lanes 0-15 own the 16 pixels) ----
        {
            const float dy = offb[(size_t)(2 * k) * ostr];
            const float dx = offb[(size_t)(2 * k + 1) * ostr];
            const int dky = k / 3 - 1;
            const int dkx = k - (k / 3) * 3 - 1;
            const float ys = dy + (float)(myh + dky);
            const float xs = dx + (float)(myw + dkx);

            const float y0f = floorf(ys), x0f = floorf(xs);
            const int iy0 = (int)y0f, ix0 = (int)x0f;
            const int iy1 = iy0 + 1,  ix1 = ix0 + 1;
            const float fy = ys - y0f, fx = xs - x0f;
            const float gy = 1.f - fy, gx = 1.f - fx;

            const bool vy0 = (unsigned)iy0 < Hh;
            const bool vy1 = (unsigned)iy1 < Hh;
            const bool vx0 = (unsigned)ix0 < Ww;
            const bool vx1 = (unsigned)ix1 < Ww;
            const int cy0 = min(max(iy0, 0), Hh - 1);
            const int cy1 = min(max(iy1, 0), Hh - 1);
            const int cx0 = min(max(ix0, 0), Ww - 1);
            const int cx1 = min(max(ix1, 0), Ww - 1);

            uint4 wq, iq;
            wq.x = __float_as_uint((vy0 && vx0) ? gy * gx : 0.f);
            wq.y = __float_as_uint((vy0 && vx1) ? gy * fx : 0.f);
            wq.z = __float_as_uint((vy1 && vx0) ? fy * gx : 0.f);
            wq.w = __float_as_uint((vy1 && vx1) ? fy * fx : 0.f);
            iq.x = (uint32_t)(cy0 * Ww + cx0);
            iq.y = (uint32_t)(cy0 * Ww + cx1);
            iq.z = (uint32_t)(cy1 * Ww + cx0);
            iq.w = (uint32_t)(cy1 * Ww + cx1);
            if (lane < 16) {
                *(uint4*)(sp + lane * PPAD)     = wq;
                *(uint4*)(sp + lane * PPAD + 4) = iq;
            }
        }
        __syncwarp();

        // ---- Phase B: gather + combine straight into A fragment registers ----
        uint32_t f0, f1, f2, f3, f4_, f5, f6, f7;
        {   // pixel g  -> a0 (ks0), a2 (ks0), a0 (ks1), a2 (ks1)
            const uint4 wq = *(const uint4*)(sp + g * PPAD);
            const uint4 iq = *(const uint4*)(sp + g * PPAD + 4);
            const uint4 qa = gb4[(size_t)iq.x * 4];
            const uint4 qb = gb4[(size_t)iq.y * 4];
            const uint4 qc = gb4[(size_t)iq.z * 4];
            const uint4 qd = gb4[(size_t)iq.w * 4];
            float vs[8];
            combine8(qa, qb, qc, qd, wq, vs);
            const __half2 h0 = __floats2half2_rn(vs[0], vs[1]);
            const __half2 h1 = __floats2half2_rn(vs[2], vs[3]);
            const __half2 h2 = __floats2half2_rn(vs[4], vs[5]);
            const __half2 h3 = __floats2half2_rn(vs[6], vs[7]);
            f0 = *(const uint32_t*)&h0;   // ks0 a0
            f2 = *(const uint32_t*)&h1;   // ks0 a2
            f4_ = *(const uint32_t*)&h2;  // ks1 a0
            f6 = *(const uint32_t*)&h3;   // ks1 a2
        }
        {   // pixel g+8 -> a1, a3 (both ks)
            const uint4 wq = *(const uint4*)(sp + (g + 8) * PPAD);
            const uint4 iq = *(const uint4*)(sp + (g + 8) * PPAD + 4);
            const uint4 qa = gb4[(size_t)iq.x * 4];
            const uint4 qb = gb4[(size_t)iq.y * 4];
            const uint4 qc = gb4[(size_t)iq.z * 4];
            const uint4 qd = gb4[(size_t)iq.w * 4];
            float vs[8];
            combine8(qa, qb, qc, qd, wq, vs);
            const __half2 h0 = __floats2half2_rn(vs[0], vs[1]);
            const __half2 h1 = __floats2half2_rn(vs[2], vs[3]);
            const __half2 h2 = __floats2half2_rn(vs[4], vs[5]);
            const __half2 h3 = __floats2half2_rn(vs[6], vs[7]);
            f1 = *(const uint32_t*)&h0;   // ks0 a1
            f3 = *(const uint32_t*)&h1;   // ks0 a3
            f5 = *(const uint32_t*)&h2;   // ks1 a1
            f7 = *(const uint32_t*)&h3;   // ks1 a3
        }

        // ---- MMA: D[16pix x 32cout] += A * W_k^T ----
        #pragma unroll
        for (int nt = 0; nt < 4; nt++) {
            const uint2 b0 = __ldg((const uint2*)(gwf + (((k * 2 + 0) * 4 + nt) << 6)));
            mma_f16(acc[nt], f0, f1, f2, f3, b0.x, b0.y);
        }
        #pragma unroll
        for (int nt = 0; nt < 4; nt++) {
            const uint2 b1 = __ldg((const uint2*)(gwf + (((k * 2 + 1) * 4 + nt) << 6)));
            mma_f16(acc[nt], f4_, f5, f6, f7, b1.x, b1.y);
        }
        __syncwarp();
    }

    // Epilogue: stage D[cout][pix] in smem, coalesced STG.128.
    __syncthreads();
    float* sd = (float*)smem;
    {
        const int tq = lane & 3;
        const int pixb = wid * 16 + g;
        #pragma unroll
        for (int nt = 0; nt < 4; nt++) {
            const int row = nt * 8 + 2 * tq;
            sd[row * DPAD + pixb]           = acc[nt][0];
            sd[(row + 1) * DPAD + pixb]     = acc[nt][1];
            sd[row * DPAD + pixb + 8]       = acc[nt][2];
            sd[(row + 1) * DPAD + pixb + 8] = acc[nt][3];
        }
    }
    __syncthreads();
    #pragma unroll
    for (int i = 0; i < 4; i++) {
        const int j = tid + 256 * i;       // j < 1024
        const int row = j >> 5;            // cout
        const int q = j & 31;              // float4 index within 128 pixels
        const float4 v = *(const float4*)(sd + row * DPAD + q * 4);
        *(float4*)(out + ((size_t)(b * Cc + row) * Tt + t) * HWsz + pix0 + q * 4) = v;
    }
}

extern "C" void kernel_launch(void* const* d_in, const int* in_sizes, int n_in,
                              void* d_out, int out_size) {
    const float* feat   = (const float*)d_in[0];
    const float* offset = (const float*)d_in[1];
    const float* weight = (const float*)d_in[2];
    float* out = (float*)d_out;

    cudaFuncSetAttribute(dcn_main, cudaFuncAttributeMaxDynamicSharedMemorySize, SM_TOTAL);

    prep_k<<<dim3(289, 16), 256>>>(feat, weight);
    dcn_main<<<dim3(HWsz / 128, 16), 256, SM_TOTAL>>>(offset, out);
}

// round 15
// speedup vs baseline: 1.3364x; 1.3364x over previous
#include <cuda_runtime.h>
#include <cuda_fp16.h>
#include <cstdint>

#define Hh 192
#define Ww 192
#define HWsz (192*192)
#define Cc 32
#define Tt 8
#define KK 9

// Channels-last fp16 scratch: [B][T][HW][C], linear channel order.  (37.7 MB)
__device__ __half g_scratch_h[(size_t)2 * Tt * HWsz * Cc];
// fp16 weights in m16n8k16 fragment order: [t][tap][ks(2)][nt(4)][lane(32)][2]
__device__ uint32_t g_wfrag[(size_t)Tt * KK * 2 * 4 * 32 * 2];

__device__ __forceinline__ void mma_f16(float* c, uint32_t a0, uint32_t a1,
                                        uint32_t a2, uint32_t a3,
                                        uint32_t b0, uint32_t b1) {
    asm volatile(
        "mma.sync.aligned.m16n8k16.row.col.f32.f16.f16.f32 "
        "{%0,%1,%2,%3}, {%4,%5,%6,%7}, {%8,%9}, {%0,%1,%2,%3};"
        : "+f"(c[0]), "+f"(c[1]), "+f"(c[2]), "+f"(c[3])
        : "r"(a0), "r"(a1), "r"(a2), "r"(a3), "r"(b0), "r"(b1));
}

// Per-pixel bilinear params (weights + clamped corner indices).
__device__ __forceinline__ void bparams(float dy, float dx, int h, int w,
                                        int dky, int dkx, float4& wq, int4& iq) {
    const float ys = dy + (float)(h + dky);
    const float xs = dx + (float)(w + dkx);
    const float y0f = floorf(ys), x0f = floorf(xs);
    const int iy0 = (int)y0f, ix0 = (int)x0f;
    const int iy1 = iy0 + 1,  ix1 = ix0 + 1;
    const float fy = ys - y0f, fx = xs - x0f;
    const float gy = 1.f - fy, gx = 1.f - fx;
    const bool vy0 = (unsigned)iy0 < Hh;
    const bool vy1 = (unsigned)iy1 < Hh;
    const bool vx0 = (unsigned)ix0 < Ww;
    const bool vx1 = (unsigned)ix1 < Ww;
    const int cy0 = min(max(iy0, 0), Hh - 1);
    const int cy1 = min(max(iy1, 0), Hh - 1);
    const int cx0 = min(max(ix0, 0), Ww - 1);
    const int cx1 = min(max(ix1, 0), Ww - 1);
    wq.x = (vy0 && vx0) ? gy * gx : 0.f;
    wq.y = (vy0 && vx1) ? gy * fx : 0.f;
    wq.z = (vy1 && vx0) ? fy * gx : 0.f;
    wq.w = (vy1 && vx1) ? fy * fx : 0.f;
    iq.x = cy0 * Ww + cx0;
    iq.y = cy0 * Ww + cx1;
    iq.z = cy1 * Ww + cx0;
    iq.w = cy1 * Ww + cx1;
}

// Bilinear-combine one pixel's 8 channels (this lane's quad) from 4 corner slices.
__device__ __forceinline__ void combine8(const uint4& qa, const uint4& qb,
                                         const uint4& qc, const uint4& qd,
                                         const float4& wq, float* vs) {
    #pragma unroll
    for (int j = 0; j < 4; j++) {
        const float2 fa = __half22float2(((const __half2*)&qa)[j]);
        const float2 fb = __half22float2(((const __half2*)&qb)[j]);
        const float2 fc = __half22float2(((const __half2*)&qc)[j]);
        const float2 fd = __half22float2(((const __half2*)&qd)[j]);
        vs[2 * j]     = fmaf(wq.x, fa.x, fmaf(wq.y, fb.x, fmaf(wq.z, fc.x, wq.w * fd.x)));
        vs[2 * j + 1] = fmaf(wq.x, fa.y, fmaf(wq.y, fb.y, fmaf(wq.z, fc.y, wq.w * fd.y)));
    }
}

// ---------- Kernel 1: transpose 128hw x 32c tiles (+ weight prep at x==288) ----------
#define TSTRIDE 133
__global__ __launch_bounds__(256) void prep_k(const float* __restrict__ feat,
                                              const float* __restrict__ weight) {
    if (blockIdx.x == 288) {
        const int t = blockIdx.y >> 1;
        const int half = blockIdx.y & 1;
        for (int it = half * 9; it < half * 9 + 9; it++) {
            const int j = it * 256 + threadIdx.x;    // j < 4608
            const int reg  = j & 1;
            const int lane = (j >> 1) & 31;
            const int nt   = (j >> 6) & 3;
            const int ks   = (j >> 8) & 1;
            const int tap  = j >> 9;                 // 0..8
            const int r0 = lane >> 2, c0 = lane & 3;
            const int cout = nt * 8 + r0;
            const int cin0 = ks * 16 + 2 * c0 + reg * 8;
            const float w0 = weight[((size_t)(t * Cc + cout) * Cc + cin0) * KK + tap];
            const float w1 = weight[((size_t)(t * Cc + cout) * Cc + cin0 + 1) * KK + tap];
            const __half2 h = __floats2half2_rn(w0, w1);
            g_wfrag[(size_t)t * 4608 + j] = *(const uint32_t*)&h;
        }
        return;
    }
    __shared__ float tl[32 * TSTRIDE];
    const int tid = threadIdx.x;
    const int bt = blockIdx.y;
    const int b = bt >> 3, t = bt & 7;
    const int hw0 = blockIdx.x * 128;

    const int c  = tid >> 3;
    const int f4 = tid & 7;
    const float* fsrc = feat + ((size_t)(b * Cc + c) * Tt + t) * HWsz + hw0;
    #pragma unroll
    for (int j = 0; j < 4; j++) {
        const float4 v = *(const float4*)(fsrc + (f4 + 8 * j) * 4);
        const int col = (f4 + 8 * j) * 4;
        tl[c * TSTRIDE + col]     = v.x;
        tl[c * TSTRIDE + col + 1] = v.y;
        tl[c * TSTRIDE + col + 2] = v.z;
        tl[c * TSTRIDE + col + 3] = v.w;
    }
    __syncthreads();

    uint32_t* gdst = (uint32_t*)g_scratch_h + ((size_t)bt * HWsz + hw0) * 16;
    #pragma unroll
    for (int jj = 0; jj < 2; jj++) {
        const int u4 = tid + 256 * jj;   // 0..511
        const int hw = u4 >> 2;
        const int cp4 = u4 & 3;          // channel-octet
        uint4 o;
        uint32_t* op = &o.x;
        #pragma unroll
        for (int q = 0; q < 4; q++) {
            const int ch = cp4 * 8 + 2 * q;
            const __half2 h = __floats2half2_rn(tl[ch * TSTRIDE + hw],
                                                tl[(ch + 1) * TSTRIDE + hw]);
            op[q] = *(const uint32_t*)&h;
        }
        *(uint4*)(gdst + hw * 16 + cp4 * 4) = o;
    }
}

// ---------- Kernel 2: fused deform-sample + mma.sync fp16 GEMM ----------
// Per-warp tile: 16 pixels x 32 cout. CTA = 8 warps = 128 pixels.
// Params computed per-lane in registers (4x redundant across quad lanes);
// A staged via STS.128 -> ldmatrix (the MLP-preserving buffer, per R13/R14 lesson).
#define APAD2 20      // A slab row pitch: 20 u32 = 80 B
#define DPAD 132
#define SM_TOTAL 16896   // epilogue D 32x132 f32; A slabs (10240B) fit inside

__global__ __launch_bounds__(256, 4) void dcn_main(
    const float* __restrict__ offset,   // [B, 18, T, H, W]
    float* __restrict__ out)            // [B, 32, T, H, W]
{
    extern __shared__ char smem[];
    const int tid  = threadIdx.x;
    const int wid  = tid >> 5;
    const int lane = tid & 31;
    const int bt = blockIdx.y;
    const int b = bt >> 3, t = bt & 7;
    const int pix0  = blockIdx.x * 128;
    const int pixw0 = pix0 + wid * 16;
    const int g  = lane >> 2;            // this lane's pixel pair: g and g+8

    uint32_t* sa = (uint32_t*)smem + wid * (16 * APAD2);   // fp16 A slab
    const uint32_t sa_sh = (uint32_t)__cvta_generic_to_shared(sa);
    const uint32_t* gwf = g_wfrag + (size_t)t * 4608 + lane * 2;
    // Gather base: this lane's channel-quad 16B slice of each 64B pixel row.
    const uint4* gb4 = (const uint4*)g_scratch_h + (size_t)bt * HWsz * 4 + (lane & 3);

    const float* off0 = offset + ((size_t)b * 2 * KK * Tt + t) * HWsz + pixw0 + g;
    const size_t ostr = (size_t)Tt * HWsz;

    const int pg0 = pixw0 + g;
    const int h0 = (int)((unsigned)pg0 / Ww);
    const int w0 = pg0 - h0 * Ww;
    const int pg1 = pg0 + 8;
    const int h1 = (int)((unsigned)pg1 / Ww);
    const int w1 = pg1 - h1 * Ww;

    float acc[4][4];
    #pragma unroll
    for (int n = 0; n < 4; n++)
        #pragma unroll
        for (int r = 0; r < 4; r++) acc[n][r] = 0.f;

    #pragma unroll 1
    for (int k = 0; k < KK; k++) {
        const int dky = k / 3 - 1;
        const int dkx = k - (k / 3) * 3 - 1;
        const float* ok0 = off0 + (size_t)(2 * k) * ostr;

        // ---- pixel g: params -> gather -> combine -> STS ----
        {
            float4 wq; int4 iq;
            bparams(ok0[0], ok0[ostr], h0, w0, dky, dkx, wq, iq);
            const uint4 qa = gb4[(size_t)iq.x * 4];
            const uint4 qb = gb4[(size_t)iq.y * 4];
            const uint4 qc = gb4[(size_t)iq.z * 4];
            const uint4 qd = gb4[(size_t)iq.w * 4];
            float vs[8];
            combine8(qa, qb, qc, qd, wq, vs);
            uint4 o;
            ((__half2*)&o)[0] = __floats2half2_rn(vs[0], vs[1]);
            ((__half2*)&o)[1] = __floats2half2_rn(vs[2], vs[3]);
            ((__half2*)&o)[2] = __floats2half2_rn(vs[4], vs[5]);
            ((__half2*)&o)[3] = __floats2half2_rn(vs[6], vs[7]);
            *(uint4*)(sa + g * APAD2 + (lane & 3) * 4) = o;
        }
        // ---- pixel g+8: params -> gather -> combine -> STS ----
        {
            float4 wq; int4 iq;
            bparams(ok0[8], ok0[ostr + 8], h1, w1, dky, dkx, wq, iq);
            const uint4 qa = gb4[(size_t)iq.x * 4];
            const uint4 qb = gb4[(size_t)iq.y * 4];
            const uint4 qc = gb4[(size_t)iq.z * 4];
            const uint4 qd = gb4[(size_t)iq.w * 4];
            float vs[8];
            combine8(qa, qb, qc, qd, wq, vs);
            uint4 o;
            ((__half2*)&o)[0] = __floats2half2_rn(vs[0], vs[1]);
            ((__half2*)&o)[1] = __floats2half2_rn(vs[2], vs[3]);
            ((__half2*)&o)[2] = __floats2half2_rn(vs[4], vs[5]);
            ((__half2*)&o)[3] = __floats2half2_rn(vs[6], vs[7]);
            *(uint4*)(sa + (g + 8) * APAD2 + (lane & 3) * 4) = o;
        }
        __syncwarp();

        // ---- MMA: A frags via ldmatrix.x4; D[16pix x 32cout] ----
        #pragma unroll
        for (int ks = 0; ks < 2; ks++) {
            uint32_t a0_, a1_, a2_, a3_;
            const uint32_t lmaddr = sa_sh + (lane & 15) * (APAD2 * 4)
                                          + (lane >> 4) * 16 + ks * 32;
            asm volatile(
                "ldmatrix.sync.aligned.m8n8.x4.shared.b16 {%0,%1,%2,%3}, [%4];"
                : "=r"(a0_), "=r"(a1_), "=r"(a2_), "=r"(a3_) : "r"(lmaddr));
            #pragma unroll
            for (int nt = 0; nt < 4; nt++) {
                const uint2 bb = __ldg((const uint2*)(gwf + (((k * 2 + ks) * 4 + nt) << 6)));
                mma_f16(acc[nt], a0_, a1_, a2_, a3_, bb.x, bb.y);
            }
        }
        __syncwarp();
    }

    // Epilogue: stage D[cout][pix] in smem, coalesced STG.128.
    __syncthreads();
    float* sd = (float*)smem;
    {
        const int tq = lane & 3;
        const int pixb = wid * 16 + g;
        #pragma unroll
        for (int nt = 0; nt < 4; nt++) {
            const int row = nt * 8 + 2 * tq;
            sd[row * DPAD + pixb]           = acc[nt][0];
            sd[(row + 1) * DPAD + pixb]     = acc[nt][1];
            sd[row * DPAD + pixb + 8]       = acc[nt][2];
            sd[(row + 1) * DPAD + pixb + 8] = acc[nt][3];
        }
    }
    __syncthreads();
    #pragma unroll
    for (int i = 0; i < 4; i++) {
        const int j = tid + 256 * i;       // j < 1024
        const int row = j >> 5;            // cout
        const int q = j & 31;              // float4 index within 128 pixels
        const float4 v = *(const float4*)(sd + row * DPAD + q * 4);
        *(float4*)(out + ((size_t)(b * Cc + row) * Tt + t) * HWsz + pix0 + q * 4) = v;
    }
}

extern "C" void kernel_launch(void* const* d_in, const int* in_sizes, int n_in,
                              void* d_out, int out_size) {
    const float* feat   = (const float*)d_in[0];
    const float* offset = (const float*)d_in[1];
    const float* weight = (const float*)d_in[2];
    float* out = (float*)d_out;

    cudaFuncSetAttribute(dcn_main, cudaFuncAttributeMaxDynamicSharedMemorySize, SM_TOTAL);

    prep_k<<<dim3(289, 16), 256>>>(feat, weight);
    dcn_main<<<dim3(HWsz / 128, 16), 256, SM_TOTAL>>>(offset, out);
}